// round 17
// baseline (speedup 1.0000x reference)
#include <cuda_runtime.h>
#include <cuda_bf16.h>

#define IN_DIM 128
#define OUT_DIM 64
#define N_MAX 100000
#define E_MAX 1600000
#define NEG_SLOPE 0.2f

// ---------------- scratch (static device globals: allocation-free) ----------
__device__ float d_h[(size_t)N_MAX * OUT_DIM];   // transformed features
__device__ float d_as[N_MAX];                    // h @ att_src
__device__ float d_ad[N_MAX];                    // h @ att_dst
__device__ int   d_deg[N_MAX];                   // in-degree histogram
__device__ int   d_excl[N_MAX];                  // tile-local exclusive prefix
__device__ int   d_bsum[128];                    // per-tile totals
__device__ int   d_start[N_MAX + 1];             // CSR row offsets (by dst)
__device__ int   d_cursor[N_MAX];                // placement cursors
__device__ int2  d_rec[E_MAX];                   // bucketed (src, w-as-bits)
__device__ int   d_is64;                         // edge_index dtype flag

__device__ __forceinline__ float lrelu(float v) {
    return v > 0.f ? v : NEG_SLOPE * v;
}

// ---------------- K0: detect edge_index element width ------------------------
__global__ void k0_detect(const long long* __restrict__ ei, int N)
{
    int ok64 = 1;
    for (int i = 0; i < 64; i++) {
        long long v = ei[i];
        if (v < 0 || v >= (long long)N) { ok64 = 0; break; }
    }
    d_is64 = ok64;
}

// ---------------- K2a: dst-degree histogram ----------------------------------
__global__ __launch_bounds__(256) void k2a_hist(
    const void* __restrict__ ei_raw, int E, int N)
{
    int i = blockIdx.x * blockDim.x + threadIdx.x;
    if (i >= E) return;
    int d;
    if (d_is64) {
        d = (int)((const long long*)ei_raw)[(size_t)E + i];
    } else {
        d = ((const int*)ei_raw)[(size_t)E + i];
    }
    if ((unsigned)d >= (unsigned)N) d = 0;
    atomicAdd(&d_deg[d], 1);
}

// ---------------- kS1: per-tile scan ------------------------------------------
__global__ __launch_bounds__(1024) void kS1_tile_scan(int N)
{
    __shared__ int sh[1024];
    int t = threadIdx.x;
    int gi = blockIdx.x * 1024 + t;
    int v = (gi < N) ? d_deg[gi] : 0;
    sh[t] = v;
    __syncthreads();
#pragma unroll
    for (int off = 1; off < 1024; off <<= 1) {
        int u = (t >= off) ? sh[t - off] : 0;
        __syncthreads();
        sh[t] += u;
        __syncthreads();
    }
    if (gi < N) d_excl[gi] = sh[t] - v;
    if (t == 1023) d_bsum[blockIdx.x] = sh[t];
}

// ---------------- K1: 8x4 register-tile GEMM, 3 CTAs/SM ----------------------
// 256 threads: rg = t>>4 (16 groups x 8 rows = 128 rows/block), cg = t&15
// (16 groups x 4 cols = 64 cols). Per k: 1 LDS.128 + 32 FMA (32 FMA/LDS),
// ~80 regs -> 3 CTAs/SM. Attention epilogue lives in kA.
__global__ __launch_bounds__(256, 3) void k1_gemm(
    const float* __restrict__ x, const float* __restrict__ W, int N)
{
    __shared__ float Wc[IN_DIM * OUT_DIM];   // 32 KB, [k][c] row-major

    int t = threadIdx.x;
    {
        const float4* Wg = reinterpret_cast<const float4*>(W);
        float4* Ws = reinterpret_cast<float4*>(Wc);
        for (int i = t; i < IN_DIM * OUT_DIM / 4; i += 256) Ws[i] = Wg[i];
    }
    __syncthreads();

    int cg = t & 15;
    int rg = t >> 4;
    int row0 = blockIdx.x * 128 + rg * 8;

    float4 acc[8];
#pragma unroll
    for (int r = 0; r < 8; r++) acc[r] = make_float4(0.f, 0.f, 0.f, 0.f);

    const float4* x4  = reinterpret_cast<const float4*>(x);
    const float4* Wc4 = reinterpret_cast<const float4*>(Wc);

    for (int kq = 0; kq < IN_DIM / 4; kq++) {       // 32 k-quads
        float4 xr[8];
#pragma unroll
        for (int r = 0; r < 8; r++) {
            int gr = row0 + r;
            xr[r] = (gr < N) ? x4[(size_t)gr * 32 + kq]
                             : make_float4(0.f, 0.f, 0.f, 0.f);
        }
#pragma unroll
        for (int kk = 0; kk < 4; kk++) {
            int k = kq * 4 + kk;
            float4 w = Wc4[k * 16 + cg];
#pragma unroll
            for (int r = 0; r < 8; r++) {
                float xv = (kk == 0) ? xr[r].x : (kk == 1) ? xr[r].y
                         : (kk == 2) ? xr[r].z : xr[r].w;
                acc[r].x = fmaf(xv, w.x, acc[r].x);
                acc[r].y = fmaf(xv, w.y, acc[r].y);
                acc[r].z = fmaf(xv, w.z, acc[r].z);
                acc[r].w = fmaf(xv, w.w, acc[r].w);
            }
        }
    }

    float4* h4 = reinterpret_cast<float4*>(d_h);
#pragma unroll
    for (int r = 0; r < 8; r++) {
        int gr = row0 + r;
        if (gr < N) h4[(size_t)gr * 16 + cg] = acc[r];
    }
}

// ---------------- kA: attention dots a_s = h@att_src, a_d = h@att_dst --------
__global__ __launch_bounds__(256) void kA_dots(
    const float* __restrict__ att_src, const float* __restrict__ att_dst, int N)
{
    int n = blockIdx.x * blockDim.x + threadIdx.x;
    if (n >= N) return;
    const float4* h4 = reinterpret_cast<const float4*>(d_h) + (size_t)n * 16;
    const float4* As = reinterpret_cast<const float4*>(att_src);
    const float4* Ad = reinterpret_cast<const float4*>(att_dst);
    float ps = 0.f, pd = 0.f;
#pragma unroll
    for (int i = 0; i < 16; i++) {
        float4 hv = h4[i];
        float4 a = As[i];
        float4 b = Ad[i];
        ps += hv.x * a.x + hv.y * a.y + hv.z * a.z + hv.w * a.w;
        pd += hv.x * b.x + hv.y * b.y + hv.z * b.z + hv.w * b.w;
    }
    d_as[n] = ps;
    d_ad[n] = pd;
}

// ---------------- kS23: finalize offsets + zero histogram --------------------
__global__ __launch_bounds__(256) void kS23_finalize(int N, int E, int nTiles)
{
    __shared__ int sh[128];
    int t = threadIdx.x;
    if (t < 128) sh[t] = (t < nTiles) ? d_bsum[t] : 0;
    __syncthreads();
    if (t == 0) {
        int run = 0;
        for (int i = 0; i < nTiles; i++) {
            int v = sh[i];
            sh[i] = run;
            run += v;
        }
    }
    __syncthreads();

    int i = blockIdx.x * blockDim.x + t;
    if (i < N) {
        int s = d_excl[i] + sh[i >> 10];
        d_start[i]  = s;
        d_cursor[i] = s;
        d_deg[i]    = 0;
    }
    if (i == 0) d_start[N] = E;
}

// ---------------- K2c: decode + weight + place --------------------------------
__global__ __launch_bounds__(256) void k2c_place(
    const void* __restrict__ ei_raw, int E, int N)
{
    int i = blockIdx.x * blockDim.x + threadIdx.x;
    if (i >= E) return;
    int s, d;
    if (d_is64) {
        const long long* p = (const long long*)ei_raw;
        s = (int)p[i];
        d = (int)p[(size_t)E + i];
    } else {
        const int* p = (const int*)ei_raw;
        s = p[i];
        d = p[(size_t)E + i];
    }
    if ((unsigned)s >= (unsigned)N) s = 0;
    if ((unsigned)d >= (unsigned)N) d = 0;

    float w = __expf(lrelu(d_as[s] + d_ad[d]));
    int p = atomicAdd(&d_cursor[d], 1);
    d_rec[p] = make_int2(s, __float_as_int(w));
}

// ---------------- K5: gather-aggregate, half-warp float4 (R13 form) ----------
__global__ __launch_bounds__(256) void k5_gather(
    float4* __restrict__ out, const float* __restrict__ bias, int N)
{
    int t = threadIdx.x;
    int warp = t >> 5, lane = t & 31;
    int half = lane >> 4;
    int hl   = lane & 15;
    int n = blockIdx.x * 8 + warp;
    if (n >= N) return;

    const float4* h4 = reinterpret_cast<const float4*>(d_h);

    float wself = __expf(lrelu(d_as[n] + d_ad[n]));
    float4 hv = h4[(size_t)n * 16 + hl];
    float4 acc;
    float wsum;
    if (half == 0) {
        acc = make_float4(wself * hv.x, wself * hv.y, wself * hv.z, wself * hv.w);
        wsum = wself;
    } else {
        acc = make_float4(0.f, 0.f, 0.f, 0.f);
        wsum = 0.f;
    }

    int beg = d_start[n], end = d_start[n + 1];
    int j = beg;
    for (; j + 4 <= end; j += 4) {
        int2 rA = d_rec[j + half];
        int2 rB = d_rec[j + 2 + half];
        float4 vA = h4[(size_t)rA.x * 16 + hl];
        float4 vB = h4[(size_t)rB.x * 16 + hl];
        float wA = __int_as_float(rA.y);
        float wB = __int_as_float(rB.y);
        acc.x = fmaf(wA, vA.x, acc.x); acc.y = fmaf(wA, vA.y, acc.y);
        acc.z = fmaf(wA, vA.z, acc.z); acc.w = fmaf(wA, vA.w, acc.w);
        acc.x = fmaf(wB, vB.x, acc.x); acc.y = fmaf(wB, vB.y, acc.y);
        acc.z = fmaf(wB, vB.z, acc.z); acc.w = fmaf(wB, vB.w, acc.w);
        wsum += wA + wB;
    }
    if (j + 2 <= end) {
        int2 r = d_rec[j + half];
        float4 v = h4[(size_t)r.x * 16 + hl];
        float w = __int_as_float(r.y);
        acc.x = fmaf(w, v.x, acc.x); acc.y = fmaf(w, v.y, acc.y);
        acc.z = fmaf(w, v.z, acc.z); acc.w = fmaf(w, v.w, acc.w);
        wsum += w;
        j += 2;
    }
    if (j < end) {
        int2 r = d_rec[j];
        float w = (half == 0) ? __int_as_float(r.y) : 0.f;
        float4 v = h4[(size_t)r.x * 16 + hl];
        acc.x = fmaf(w, v.x, acc.x); acc.y = fmaf(w, v.y, acc.y);
        acc.z = fmaf(w, v.z, acc.z); acc.w = fmaf(w, v.w, acc.w);
        wsum += w;
    }

    wsum  += __shfl_xor_sync(0xffffffffu, wsum,  16);
    acc.x += __shfl_xor_sync(0xffffffffu, acc.x, 16);
    acc.y += __shfl_xor_sync(0xffffffffu, acc.y, 16);
    acc.z += __shfl_xor_sync(0xffffffffu, acc.z, 16);
    acc.w += __shfl_xor_sync(0xffffffffu, acc.w, 16);

    if (half == 0) {
        float inv = 1.f / wsum;
        float4 b = reinterpret_cast<const float4*>(bias)[hl];
        out[(size_t)n * 16 + hl] = make_float4(acc.x * inv + b.x,
                                               acc.y * inv + b.y,
                                               acc.z * inv + b.z,
                                               acc.w * inv + b.w);
    }
}

// ---------------- launch ------------------------------------------------------
extern "C" void kernel_launch(void* const* d_in, const int* in_sizes, int n_in,
                              void* d_out, int out_size)
{
    const float* x    = (const float*)d_in[0];
    const void*  ei   = d_in[1];
    const float* W    = (const float*)d_in[2];
    const float* asrc = (const float*)d_in[3];
    const float* adst = (const float*)d_in[4];
    const float* bias = (const float*)d_in[5];
    float*       out  = (float*)d_out;

    int N = in_sizes[0] / IN_DIM;
    int E = in_sizes[1] / 2;
    int nTiles = (N + 1023) / 1024;

    k0_detect<<<1, 1>>>((const long long*)ei, N);
    k2a_hist<<<(E + 255) / 256, 256>>>(ei, E, N);
    kS1_tile_scan<<<nTiles, 1024>>>(N);
    k1_gemm<<<(N + 127) / 128, 256>>>(x, W, N);               // 4th: profiled
    kA_dots<<<(N + 255) / 256, 256>>>(asrc, adst, N);
    kS23_finalize<<<(N + 255) / 256, 256>>>(N, E, nTiles);
    k2c_place<<<(E + 255) / 256, 256>>>(ei, E, N);
    k5_gather<<<(N + 7) / 8, 256>>>((float4*)out, bias, N);
}